// round 6
// baseline (speedup 1.0000x reference)
#include <cuda_runtime.h>

// Problem: B=16, U=64, W=32, E=300, H=512, Hh=512, C=7, D=1024, N=B*U=1024
// Inputs (metadata order):
// 0 x, 1..8 lstm {Wih_f,Whh_f,bih_f,bhh_f,Wih_b,Whh_b,bih_b,bhh_b},
// 9..12 gg {Wih,Whh,bih,bhh}, 13 Wg, 14..17 pg, 18..21 eg, 22 cls_W, 23 cls_b
// Output: (16,64,7) float32

// ------------------------------ scratch (static device) --------------------
__device__ float g_h[2][1024][512];
__device__ float g_c[2][1024][512];
__device__ float g_gates[2][1024][2048];
__device__ float g_feat[1024][1024];
__device__ float g_Agg[64][16][3072];   // u@gg_Wih^T + gg_bih  (rows u*16+b)
__device__ float g_Apg[64][16][3072];   // u@pg_Wih^T + pg_bih
__device__ float g_q[64][16][1024];     // u@Wg
__device__ float g_hist[65][16][1024];
__device__ float g_p0[16][1024];
__device__ float g_p1[16][1024];
__device__ float g_e[16][512];
__device__ float g_ctx[16][1024];
__device__ float g_es[64][16][512];
__device__ float g_P1a[4][16][3072];
__device__ float g_P1b[4][16][3072];
__device__ float g_P2a[4][16][3072];
__device__ float g_P2b[4][16][3072];
__device__ float g_P3a[4][16][1536];
__device__ float g_P3b[4][16][1536];

// ------------------------------ helpers ------------------------------------
__device__ __forceinline__ unsigned long long pk2(float v) {
    unsigned long long r;
    asm("mov.b64 %0, {%1, %1};" : "=l"(r) : "f"(v));
    return r;
}
__device__ __forceinline__ unsigned long long fma2(unsigned long long a,
                                                   unsigned long long b,
                                                   unsigned long long c) {
    unsigned long long d;
    asm("fma.rn.f32x2 %0, %1, %2, %3;" : "=l"(d) : "l"(a), "l"(b), "l"(c));
    return d;
}
__device__ __forceinline__ float2 upk2(unsigned long long v) {
    float2 f;
    asm("mov.b64 {%0, %1}, %2;" : "=f"(f.x), "=f"(f.y) : "l"(v));
    return f;
}
__device__ __forceinline__ float sigf(float x) {
    return 1.0f / (1.0f + __expf(-x));
}
__device__ __forceinline__ float tanhfast(float x) {
    return 2.0f / (1.0f + __expf(-2.0f * x)) - 1.0f;
}

// ------------------------------ zero init ----------------------------------
__global__ void zero_kernel() {
    int i = blockIdx.x * 256 + threadIdx.x;
    if (i < 2 * 1024 * 512) {
        (&g_h[0][0][0])[i] = 0.0f;
        (&g_c[0][0][0])[i] = 0.0f;
    }
    if (i < 65 * 16 * 1024) (&g_hist[0][0][0])[i] = 0.0f;
    if (i < 16 * 1024) {
        (&g_p0[0][0])[i] = 0.0f;
        (&g_p1[0][0])[i] = 0.0f;
    }
    if (i < 16 * 512) (&g_e[0][0])[i] = 0.0f;
}

// ------------------------------ LSTM step GEMM -----------------------------
// gates[dir][n][j] = sum_e x[n,tt,e]*Wih[j,e] + sum_k h[dir][n,k]*Whh[j,k]
//                    + bih[j] + bhh[j]
// BM=128, BN=128, BK=16, 256 threads, 8x8 per thread, f32x2 packed cols.
__global__ __launch_bounds__(256) void lstm_gemm(
    const float* __restrict__ x,
    const float* __restrict__ Wih_f, const float* __restrict__ Whh_f,
    const float* __restrict__ bih_f, const float* __restrict__ bhh_f,
    const float* __restrict__ Wih_b, const float* __restrict__ Whh_b,
    const float* __restrict__ bih_b, const float* __restrict__ bhh_b,
    int t)
{
    const int dir = blockIdx.z;
    const float* Wih = dir ? Wih_b : Wih_f;
    const float* Whh = dir ? Whh_b : Whh_f;
    const float* bih = dir ? bih_b : bih_f;
    const float* bhh = dir ? bhh_b : bhh_f;
    const int tt = dir ? (31 - t) : t;
    const float* A1 = x + tt * 300;          // [n][e], row stride 9600
    const float* A2 = &g_h[dir][0][0];       // [n][k], row stride 512

    __shared__ __align__(16) float As[16][130];
    __shared__ __align__(16) float Bs[16][130];

    const int tid = threadIdx.x;
    const int tx = tid & 15, ty = tid >> 4;
    const int m0 = blockIdx.y * 128;
    const int j0 = blockIdx.x * 128;

    unsigned long long acc[8][4];
#pragma unroll
    for (int i = 0; i < 8; i++)
#pragma unroll
        for (int c = 0; c < 4; c++) acc[i][c] = 0ULL;

#pragma unroll 1
    for (int seg = 0; seg < 2; seg++) {
        const float* Ap = seg ? A2 : A1;
        const float* Wp = seg ? Whh : Wih;
        const int K   = seg ? 512 : 300;
        const int lda = seg ? 512 : 9600;
        const int ldw = seg ? 512 : 300;
        for (int k0 = 0; k0 < K; k0 += 16) {
#pragma unroll
            for (int l = 0; l < 8; l++) {
                int idx = tid + 256 * l;
                int k = idx & 15, r = idx >> 4;
                float v = 0.0f;
                if (k0 + k < K) v = Ap[(m0 + r) * lda + k0 + k];
                As[k][r] = v;
            }
#pragma unroll
            for (int l = 0; l < 8; l++) {
                int idx = tid + 256 * l;
                int k = idx & 15, j = idx >> 4;
                float v = 0.0f;
                if (k0 + k < K) v = Wp[(j0 + j) * ldw + k0 + k];
                Bs[k][j] = v;
            }
            __syncthreads();
#pragma unroll
            for (int k = 0; k < 16; k++) {
                unsigned long long bv[4];
#pragma unroll
                for (int c = 0; c < 4; c++)
                    bv[c] = *reinterpret_cast<const unsigned long long*>(
                        &Bs[k][2 * tx + 32 * c]);
#pragma unroll
                for (int i = 0; i < 8; i++) {
                    unsigned long long av = pk2(As[k][ty + 16 * i]);
#pragma unroll
                    for (int c = 0; c < 4; c++)
                        acc[i][c] = fma2(av, bv[c], acc[i][c]);
                }
            }
            __syncthreads();
        }
    }

#pragma unroll
    for (int i = 0; i < 8; i++) {
        int r = m0 + ty + 16 * i;
#pragma unroll
        for (int c = 0; c < 4; c++) {
            int j = j0 + 2 * tx + 32 * c;
            float2 v = upk2(acc[i][c]);
            g_gates[dir][r][j]     = v.x + bih[j]     + bhh[j];
            g_gates[dir][r][j + 1] = v.y + bih[j + 1] + bhh[j + 1];
        }
    }
}

// ------------------------------ LSTM pointwise -----------------------------
__global__ void lstm_point(int t) {
    int idx = blockIdx.x * 256 + threadIdx.x;   // 2*1024*512
    int dir = idx >> 19;
    int rem = idx & ((1 << 19) - 1);
    int n = rem >> 9;
    int k = rem & 511;
    float gi = g_gates[dir][n][k];
    float gf = g_gates[dir][n][512 + k];
    float gg = g_gates[dir][n][1024 + k];
    float go = g_gates[dir][n][1536 + k];
    float c = g_c[dir][n][k];
    c = sigf(gf) * c + sigf(gi) * tanhfast(gg);
    float h = sigf(go) * tanhfast(c);
    g_c[dir][n][k] = c;
    g_h[dir][n][k] = h;
    if (t == 31) g_feat[n][dir * 512 + k] = h;
}

// ------------------------------ precompute GEMM ----------------------------
// out[r][j] = sum_k feat[rowmap(r)][k] * W[k*sk + j*sj] + bias[j]
// rowmap(r) = (r&15)*64 + (r>>4)   (r = u*16+b  ->  feat row b*64+u)
// BM=64, BN=128, BK=16, 256 threads, 4x8 per thread (f32x2 cols).
__global__ __launch_bounds__(256) void pre_gemm(
    const float* __restrict__ W, const float* __restrict__ bias,
    float* __restrict__ out, int N, int sk, int sj)
{
    __shared__ __align__(16) float As[16][66];
    __shared__ __align__(16) float Bs[16][130];
    const int tid = threadIdx.x;
    const int tx = tid & 15, ty = tid >> 4;
    const int m0 = blockIdx.y * 64;
    const int j0 = blockIdx.x * 128;

    unsigned long long acc[4][4];
#pragma unroll
    for (int i = 0; i < 4; i++)
#pragma unroll
        for (int c = 0; c < 4; c++) acc[i][c] = 0ULL;

    for (int k0 = 0; k0 < 1024; k0 += 16) {
#pragma unroll
        for (int l = 0; l < 4; l++) {
            int idx = tid + 256 * l;
            int k = idx & 15, r = idx >> 4;
            int rr = m0 + r;
            int fr = (rr & 15) * 64 + (rr >> 4);
            As[k][r] = g_feat[fr][k0 + k];
        }
#pragma unroll
        for (int l = 0; l < 8; l++) {
            int idx = tid + 256 * l;
            int k = idx & 15, j = idx >> 4;
            Bs[k][j] = W[(k0 + k) * sk + (j0 + j) * sj];
        }
        __syncthreads();
#pragma unroll
        for (int k = 0; k < 16; k++) {
            unsigned long long bv[4];
#pragma unroll
            for (int c = 0; c < 4; c++)
                bv[c] = *reinterpret_cast<const unsigned long long*>(
                    &Bs[k][2 * tx + 32 * c]);
#pragma unroll
            for (int i = 0; i < 4; i++) {
                unsigned long long av = pk2(As[k][ty + 16 * i]);
#pragma unroll
                for (int c = 0; c < 4; c++)
                    acc[i][c] = fma2(av, bv[c], acc[i][c]);
            }
        }
        __syncthreads();
    }

#pragma unroll
    for (int i = 0; i < 4; i++) {
        int r = m0 + ty + 16 * i;
#pragma unroll
        for (int c = 0; c < 4; c++) {
            int j = j0 + 2 * tx + 32 * c;
            float2 v = upk2(acc[i][c]);
            float b0 = bias ? bias[j] : 0.0f;
            float b1 = bias ? bias[j + 1] : 0.0f;
            out[r * N + j]     = v.x + b0;
            out[r * N + j + 1] = v.y + b1;
        }
    }
}

// ------------------------------ per-step M=16 GEMM -------------------------
// part1[ks][16][N] += A1 @ W1^T (chunk ks), part2 likewise for A2/W2.
// Kept separate because the GRU n-gate needs gi and gh separately.
// grid (N/64, 4), 256 threads, each thread 4 rows x 1 col.
__global__ __launch_bounds__(256) void gemm16(
    const float* __restrict__ A1, const float* __restrict__ W1, int K1,
    const float* __restrict__ A2, const float* __restrict__ W2, int K2,
    float* __restrict__ part1, float* __restrict__ part2, int N)
{
    __shared__ float As[16][18];
    __shared__ float Bs[16][66];
    const int tid = threadIdx.x;
    const int col = tid & 63, rq = tid >> 6;
    const int ks = blockIdx.y;
    const int j0 = blockIdx.x * 64;

    float acc1[4] = {0.f, 0.f, 0.f, 0.f};
    float acc2[4] = {0.f, 0.f, 0.f, 0.f};

    // segment 1
    {
        int chunk = K1 >> 2, kb = ks * chunk;
        for (int k0 = 0; k0 < chunk; k0 += 16) {
            {
                int k = tid & 15, r = tid >> 4;
                As[k][r] = A1[r * K1 + kb + k0 + k];
            }
#pragma unroll
            for (int l = 0; l < 4; l++) {
                int idx = tid + 256 * l;
                int k = idx & 15, j = idx >> 4;
                Bs[k][j] = W1[(j0 + j) * K1 + kb + k0 + k];
            }
            __syncthreads();
#pragma unroll
            for (int k = 0; k < 16; k++) {
                float b = Bs[k][col];
#pragma unroll
                for (int i = 0; i < 4; i++) acc1[i] += As[k][rq * 4 + i] * b;
            }
            __syncthreads();
        }
    }
    // segment 2
    {
        int chunk = K2 >> 2, kb = ks * chunk;
        for (int k0 = 0; k0 < chunk; k0 += 16) {
            {
                int k = tid & 15, r = tid >> 4;
                As[k][r] = A2[r * K2 + kb + k0 + k];
            }
#pragma unroll
            for (int l = 0; l < 4; l++) {
                int idx = tid + 256 * l;
                int k = idx & 15, j = idx >> 4;
                Bs[k][j] = W2[(j0 + j) * K2 + kb + k0 + k];
            }
            __syncthreads();
#pragma unroll
            for (int k = 0; k < 16; k++) {
                float b = Bs[k][col];
#pragma unroll
                for (int i = 0; i < 4; i++) acc2[i] += As[k][rq * 4 + i] * b;
            }
            __syncthreads();
        }
    }

#pragma unroll
    for (int i = 0; i < 4; i++) {
        int r = rq * 4 + i;
        part1[(ks * 16 + r) * N + j0 + col] = acc1[i];
        part2[(ks * 16 + r) * N + j0 + col] = acc2[i];
    }
}

// ------------------------------ GRU combine --------------------------------
// gi = (pre ? pre[b][j..] : bih[j..]) + sum_ks part1
// gh = bhh[j..] + sum_ks part2
// r=sig(gir+ghr); z=sig(giz+ghz); n=tanh(gin + r*ghn); out=(1-z)*n + z*h
__global__ void gru_combine(
    const float* __restrict__ pre, const float* __restrict__ bih,
    const float* __restrict__ bhh,
    const float* __restrict__ part1, const float* __restrict__ part2,
    const float* __restrict__ h,
    float* __restrict__ out, float* __restrict__ out2, int Dh)
{
    int idx = blockIdx.x * 256 + threadIdx.x;
    if (idx >= 16 * Dh) return;
    int b = idx / Dh, j = idx - b * Dh;
    int G = 3 * Dh;
    float gir = 0.f, giz = 0.f, gin = 0.f;
    float ghr = 0.f, ghz = 0.f, ghn = 0.f;
#pragma unroll
    for (int ks = 0; ks < 4; ks++) {
        const float* p1 = part1 + (ks * 16 + b) * G;
        const float* p2 = part2 + (ks * 16 + b) * G;
        gir += p1[j]; giz += p1[Dh + j]; gin += p1[2 * Dh + j];
        ghr += p2[j]; ghz += p2[Dh + j]; ghn += p2[2 * Dh + j];
    }
    if (pre) {
        const float* pp = pre + b * G;
        gir += pp[j]; giz += pp[Dh + j]; gin += pp[2 * Dh + j];
    } else {
        gir += bih[j]; giz += bih[Dh + j]; gin += bih[2 * Dh + j];
    }
    ghr += bhh[j]; ghz += bhh[Dh + j]; ghn += bhh[2 * Dh + j];

    float r = sigf(gir + ghr);
    float z = sigf(giz + ghz);
    float n = tanhfast(gin + r * ghn);
    float hv = h[idx];
    float o = (1.0f - z) * n + z * hv;
    out[idx] = o;
    if (out2) out2[idx] = o;
}

// ------------------------------ attention ----------------------------------
// scores[t,b] = q[i,b] . hist[t,b] for t<=i; softmax over t; ctx = sum w*hist
__global__ void attn_kernel(int i) {
    __shared__ float q_s[1024];
    __shared__ float sc[65];
    const int b = blockIdx.x;
    const int tid = threadIdx.x;
#pragma unroll
    for (int l = 0; l < 4; l++)
        q_s[tid + 256 * l] = g_q[i][b][tid + 256 * l];
    __syncthreads();

    const int wid = tid >> 5, lane = tid & 31;
    for (int t = wid; t <= i; t += 8) {
        float s = 0.0f;
        for (int d = lane; d < 1024; d += 32)
            s += q_s[d] * g_hist[t][b][d];
#pragma unroll
        for (int o = 16; o; o >>= 1) s += __shfl_xor_sync(0xffffffffu, s, o);
        if (lane == 0) sc[t] = s;
    }
    __syncthreads();

    if (tid < 32) {
        float m = -1e30f;
        for (int t = lane; t <= i; t += 32) m = fmaxf(m, sc[t]);
#pragma unroll
        for (int o = 16; o; o >>= 1)
            m = fmaxf(m, __shfl_xor_sync(0xffffffffu, m, o));
        float s = 0.0f;
        for (int t = lane; t <= i; t += 32) {
            float e = __expf(sc[t] - m);
            sc[t] = e;
            s += e;
        }
#pragma unroll
        for (int o = 16; o; o >>= 1) s += __shfl_xor_sync(0xffffffffu, s, o);
        float inv = 1.0f / s;
        for (int t = lane; t <= i; t += 32) sc[t] *= inv;
    }
    __syncthreads();

#pragma unroll
    for (int l = 0; l < 4; l++) {
        int d = tid + 256 * l;
        float a = 0.0f;
        for (int t = 0; t <= i; t++) a += sc[t] * g_hist[t][b][d];
        g_ctx[b][d] = a;
    }
}

// ------------------------------ classifier ---------------------------------
__global__ void cls_kernel(const float* __restrict__ cls_W,
                           const float* __restrict__ cls_b,
                           float* __restrict__ out) {
    int u = blockIdx.x;
    int tid = threadIdx.x;
    if (tid >= 112) return;
    int b = tid / 7, c = tid - b * 7;
    float s = cls_b[c];
    const float* w = cls_W + c * 512;
    const float* e = &g_es[u][b][0];
    for (int k = 0; k < 512; k++) s += e[k] * w[k];
    out[(b * 64 + u) * 7 + c] = s;
}

// ------------------------------ launch -------------------------------------
extern "C" void kernel_launch(void* const* d_in, const int* in_sizes, int n_in,
                              void* d_out, int out_size) {
    const float* x       = (const float*)d_in[0];
    const float* lWih_f  = (const float*)d_in[1];
    const float* lWhh_f  = (const float*)d_in[2];
    const float* lbih_f  = (const float*)d_in[3];
    const float* lbhh_f  = (const float*)d_in[4];
    const float* lWih_b  = (const float*)d_in[5];
    const float* lWhh_b  = (const float*)d_in[6];
    const float* lbih_b  = (const float*)d_in[7];
    const float* lbhh_b  = (const float*)d_in[8];
    const float* gg_Wih  = (const float*)d_in[9];
    const float* gg_Whh  = (const float*)d_in[10];
    const float* gg_bih  = (const float*)d_in[11];
    const float* gg_bhh  = (const float*)d_in[12];
    const float* Wg      = (const float*)d_in[13];
    const float* pg_Wih  = (const float*)d_in[14];
    const float* pg_Whh  = (const float*)d_in[15];
    const float* pg_bih  = (const float*)d_in[16];
    const float* pg_bhh  = (const float*)d_in[17];
    const float* eg_Wih  = (const float*)d_in[18];
    const float* eg_Whh  = (const float*)d_in[19];
    const float* eg_bih  = (const float*)d_in[20];
    const float* eg_bhh  = (const float*)d_in[21];
    const float* cls_W   = (const float*)d_in[22];
    const float* cls_b   = (const float*)d_in[23];
    float* out = (float*)d_out;

    float *pAgg, *pApg, *pQ, *pHist, *pP0, *pP1, *pCtx, *pE, *pEs;
    float *pP1a, *pP1b, *pP2a, *pP2b, *pP3a, *pP3b;
    cudaGetSymbolAddress((void**)&pAgg,  g_Agg);
    cudaGetSymbolAddress((void**)&pApg,  g_Apg);
    cudaGetSymbolAddress((void**)&pQ,    g_q);
    cudaGetSymbolAddress((void**)&pHist, g_hist);
    cudaGetSymbolAddress((void**)&pP0,   g_p0);
    cudaGetSymbolAddress((void**)&pP1,   g_p1);
    cudaGetSymbolAddress((void**)&pCtx,  g_ctx);
    cudaGetSymbolAddress((void**)&pE,    g_e);
    cudaGetSymbolAddress((void**)&pEs,   g_es);
    cudaGetSymbolAddress((void**)&pP1a,  g_P1a);
    cudaGetSymbolAddress((void**)&pP1b,  g_P1b);
    cudaGetSymbolAddress((void**)&pP2a,  g_P2a);
    cudaGetSymbolAddress((void**)&pP2b,  g_P2b);
    cudaGetSymbolAddress((void**)&pP3a,  g_P3a);
    cudaGetSymbolAddress((void**)&pP3b,  g_P3b);

    zero_kernel<<<4160, 256>>>();

    // Phase 1: biLSTM, 32 sequential steps
    for (int t = 0; t < 32; t++) {
        dim3 g(16, 8, 2);   // 2048/128 cols, 1024/128 rows, 2 dirs
        lstm_gemm<<<g, 256>>>(x, lWih_f, lWhh_f, lbih_f, lbhh_f,
                              lWih_b, lWhh_b, lbih_b, lbhh_b, t);
        lstm_point<<<4096, 256>>>(t);
    }

    // Phase 2 precompute: loop-invariant projections
    pre_gemm<<<dim3(24, 16), 256>>>(gg_Wih, gg_bih, pAgg, 3072, 1, 1024);
    pre_gemm<<<dim3(24, 16), 256>>>(pg_Wih, pg_bih, pApg, 3072, 1, 1024);
    pre_gemm<<<dim3(8, 16),  256>>>(Wg, nullptr, pQ, 1024, 1024, 1);

    // Phase 2: 64 sequential utterance steps
    for (int i = 0; i < 64; i++) {
        float* p_slot = ((i & 1) == 0) ? pP0 : pP1;
        float* hist_i  = pHist + (size_t)i * 16 * 1024;
        float* hist_i1 = pHist + (size_t)(i + 1) * 16 * 1024;

        // history GRU: g_new = GRU(u+p, hist[i])
        gemm16<<<dim3(48, 4), 256>>>(p_slot, gg_Wih, 1024,
                                     hist_i, gg_Whh, 1024,
                                     pP1a, pP1b, 3072);
        gru_combine<<<64, 256>>>(pAgg + (size_t)i * 16 * 3072, nullptr, gg_bhh,
                                 pP1a, pP1b, hist_i, hist_i1, nullptr, 1024);
        // attention over history -> ctx
        attn_kernel<<<16, 256>>>(i);
        // phrase GRU: p_new = GRU(u+ctx, p)
        gemm16<<<dim3(48, 4), 256>>>(pCtx, pg_Wih, 1024,
                                     p_slot, pg_Whh, 1024,
                                     pP2a, pP2b, 3072);
        gru_combine<<<64, 256>>>(pApg + (size_t)i * 16 * 3072, nullptr, pg_bhh,
                                 pP2a, pP2b, p_slot, p_slot, nullptr, 1024);
        // emission GRU: e = GRU(p_new, e)
        gemm16<<<dim3(24, 4), 256>>>(p_slot, eg_Wih, 1024,
                                     pE, eg_Whh, 512,
                                     pP3a, pP3b, 1536);
        gru_combine<<<32, 256>>>(nullptr, eg_bih, eg_bhh,
                                 pP3a, pP3b, pE, pE,
                                 pEs + (size_t)i * 16 * 512, 512);
    }

    // classifier
    cls_kernel<<<64, 128>>>(cls_W, cls_b, out);
}

// round 7
// speedup vs baseline: 1.2440x; 1.2440x over previous
#include <cuda_runtime.h>
#include <cuda_bf16.h>

// B=16,U=64,W=32,E=300,H=512,Hh=512,C=7,D=1024,N=1024. KPAD=320+512=832.

__device__ float g_c[2][1024][512];
__device__ float g_gates[2][1024][2048];
__device__ float g_feat[1024][1024];
__device__ __nv_bfloat16 g_Xhi[32][1024][320];
__device__ __nv_bfloat16 g_Xlo[32][1024][320];
__device__ __nv_bfloat16 g_Whi[2][2048][832];
__device__ __nv_bfloat16 g_Wlo[2][2048][832];
__device__ __nv_bfloat16 g_Hhi[2][1024][512];
__device__ __nv_bfloat16 g_Hlo[2][1024][512];
__device__ float g_Agg[64][16][3072];
__device__ float g_Apg[64][16][3072];
__device__ float g_q[64][16][1024];
__device__ float g_hist[65][16][1024];
__device__ float g_p0[16][1024];
__device__ float g_p1[16][1024];
__device__ float g_e[16][512];
__device__ float g_ctx[16][1024];
__device__ float g_es[64][16][512];
__device__ float g_P1a[4][16][3072];
__device__ float g_P1b[4][16][3072];
__device__ float g_P2a[4][16][3072];
__device__ float g_P2b[4][16][3072];
__device__ float g_P3a[4][16][1536];
__device__ float g_P3b[4][16][1536];

__device__ __forceinline__ unsigned long long pk2(float v) {
    unsigned long long r; asm("mov.b64 %0, {%1, %1};" : "=l"(r) : "f"(v)); return r;
}
__device__ __forceinline__ unsigned long long fma2(unsigned long long a, unsigned long long b, unsigned long long c) {
    unsigned long long d; asm("fma.rn.f32x2 %0, %1, %2, %3;" : "=l"(d) : "l"(a), "l"(b), "l"(c)); return d;
}
__device__ __forceinline__ float2 upk2(unsigned long long v) {
    float2 f; asm("mov.b64 {%0, %1}, %2;" : "=f"(f.x), "=f"(f.y) : "l"(v)); return f;
}
__device__ __forceinline__ float sigf(float x) { return 1.0f / (1.0f + __expf(-x)); }
__device__ __forceinline__ float tanhfast(float x) { return 2.0f / (1.0f + __expf(-2.0f * x)) - 1.0f; }
__device__ __forceinline__ unsigned sm_u32(const void* p) { return (unsigned)__cvta_generic_to_shared(p); }
__device__ __forceinline__ void ldsm4(unsigned& r0, unsigned& r1, unsigned& r2, unsigned& r3, unsigned a) {
    asm volatile("ldmatrix.sync.aligned.m8n8.x4.shared.b16 {%0,%1,%2,%3},[%4];"
                 : "=r"(r0), "=r"(r1), "=r"(r2), "=r"(r3) : "r"(a));
}
__device__ __forceinline__ void mma_bf16(float c[4], unsigned a0, unsigned a1, unsigned a2, unsigned a3,
                                         unsigned b0, unsigned b1) {
    asm volatile("mma.sync.aligned.m16n8k16.row.col.f32.bf16.bf16.f32 "
                 "{%0,%1,%2,%3},{%4,%5,%6,%7},{%8,%9},{%0,%1,%2,%3};"
                 : "+f"(c[0]), "+f"(c[1]), "+f"(c[2]), "+f"(c[3])
                 : "r"(a0), "r"(a1), "r"(a2), "r"(a3), "r"(b0), "r"(b1));
}

__global__ void zero_kernel() {
    int i = blockIdx.x * 256 + threadIdx.x;
    if (i < 2 * 1024 * 512) {
        (&g_c[0][0][0])[i] = 0.0f;
        (&g_Hhi[0][0][0])[i] = __float2bfloat16(0.0f);
        (&g_Hlo[0][0][0])[i] = __float2bfloat16(0.0f);
    }
    if (i < 65 * 16 * 1024) (&g_hist[0][0][0])[i] = 0.0f;
    if (i < 16 * 1024) { (&g_p0[0][0])[i] = 0.0f; (&g_p1[0][0])[i] = 0.0f; }
    if (i < 16 * 512) (&g_e[0][0])[i] = 0.0f;
}

// split x and LSTM weights into bf16 hi/lo, K-concatenated [Wih(300)+pad20 | Whh(512)]
__global__ void convert_kernel(const float* __restrict__ x,
                               const float* __restrict__ Wfi, const float* __restrict__ Wfh,
                               const float* __restrict__ Wbi, const float* __restrict__ Wbh) {
    int i = blockIdx.x * 256 + threadIdx.x;
    if (i < 32 * 1024 * 320) {
        int e = i % 320, r = i / 320;
        int n = r % 1024, t = r / 1024;
        float v = (e < 300) ? x[n * 9600 + t * 300 + e] : 0.0f;
        __nv_bfloat16 h = __float2bfloat16(v);
        (&g_Xhi[0][0][0])[i] = h;
        (&g_Xlo[0][0][0])[i] = __float2bfloat16(v - __bfloat162float(h));
    }
    if (i < 2 * 2048 * 832) {
        int k = i % 832, r = i / 832;
        int j = r % 2048, d = r / 2048;
        const float* Wih = d ? Wbi : Wfi;
        const float* Whh = d ? Wbh : Wfh;
        float v = (k < 300) ? Wih[j * 300 + k] : (k < 320 ? 0.0f : Whh[j * 512 + (k - 320)]);
        __nv_bfloat16 h = __float2bfloat16(v);
        (&g_Whi[0][0][0])[i] = h;
        (&g_Wlo[0][0][0])[i] = __float2bfloat16(v - __bfloat162float(h));
    }
}

// Tensor-core LSTM step GEMM. gates = [x|h] @ W^T + biases, bf16 hi/lo 3-pass.
// grid (16,8,2), 256 threads. Block 128x128, warp 64x32, 52 k-tiles x 3 passes.
__global__ __launch_bounds__(256) void lstm_tc(
    const float* __restrict__ bih_f, const float* __restrict__ bhh_f,
    const float* __restrict__ bih_b, const float* __restrict__ bhh_b, int t)
{
    const int dir = blockIdx.z, m0 = blockIdx.y * 128, n0 = blockIdx.x * 128;
    const int tt = dir ? 31 - t : t;
    const float* bih = dir ? bih_b : bih_f;
    const float* bhh = dir ? bhh_b : bhh_f;
    __shared__ __nv_bfloat16 As[2][128][24];
    __shared__ __nv_bfloat16 Bs[2][128][24];
    const int tid = threadIdx.x, lane = tid & 31, wid = tid >> 5;
    const int wm = wid >> 2, wn = wid & 3;
    const int r = tid >> 1, hf = (tid & 1) * 8;

    float acc[4][4][4];
#pragma unroll
    for (int mi = 0; mi < 4; mi++)
#pragma unroll
        for (int ni = 0; ni < 4; ni++)
#pragma unroll
            for (int q = 0; q < 4; q++) acc[mi][ni][q] = 0.0f;

    uint4 ra, rb;
    auto fetch = [&](int kk) {
        int pass = kk / 52, k = (kk % 52) * 16;
        const __nv_bfloat16* ap;
        if (k < 320)
            ap = (pass == 1 ? &g_Xlo[0][0][0] : &g_Xhi[0][0][0]) + ((tt * 1024 + m0 + r) * 320 + k + hf);
        else
            ap = (pass == 1 ? &g_Hlo[0][0][0] : &g_Hhi[0][0][0]) + ((dir * 1024 + m0 + r) * 512 + (k - 320) + hf);
        const __nv_bfloat16* bp =
            (pass == 2 ? &g_Wlo[0][0][0] : &g_Whi[0][0][0]) + ((dir * 2048 + n0 + r) * 832 + k + hf);
        ra = *(const uint4*)ap;
        rb = *(const uint4*)bp;
    };

    fetch(0);
    *(uint4*)&As[0][r][hf] = ra;
    *(uint4*)&Bs[0][r][hf] = rb;
    __syncthreads();

    for (int kk = 0; kk < 156; kk++) {
        int cur = kk & 1;
        if (kk < 155) fetch(kk + 1);

        unsigned a[4][4], bfr[2][4];
#pragma unroll
        for (int mi = 0; mi < 4; mi++) {
            unsigned ad = sm_u32(&As[cur][wm * 64 + mi * 16 + (lane & 15)][(lane >> 4) * 8]);
            ldsm4(a[mi][0], a[mi][1], a[mi][2], a[mi][3], ad);
        }
#pragma unroll
        for (int nb = 0; nb < 2; nb++) {
            unsigned ad = sm_u32(&Bs[cur][wn * 32 + nb * 16 + (lane & 15)][(lane >> 4) * 8]);
            ldsm4(bfr[nb][0], bfr[nb][1], bfr[nb][2], bfr[nb][3], ad);
        }
#pragma unroll
        for (int mi = 0; mi < 4; mi++)
#pragma unroll
            for (int ni = 0; ni < 4; ni++)
                mma_bf16(acc[mi][ni], a[mi][0], a[mi][1], a[mi][2], a[mi][3],
                         bfr[ni >> 1][ni & 1], bfr[ni >> 1][(ni & 1) + 2]);

        if (kk < 155) {
            *(uint4*)&As[cur ^ 1][r][hf] = ra;
            *(uint4*)&Bs[cur ^ 1][r][hf] = rb;
        }
        __syncthreads();
    }

#pragma unroll
    for (int mi = 0; mi < 4; mi++)
#pragma unroll
        for (int ni = 0; ni < 4; ni++) {
            int m = m0 + wm * 64 + mi * 16 + (lane >> 2);
            int j = n0 + wn * 32 + ni * 8 + (lane & 3) * 2;
            float b0 = bih[j] + bhh[j], b1 = bih[j + 1] + bhh[j + 1];
            g_gates[dir][m][j]         = acc[mi][ni][0] + b0;
            g_gates[dir][m][j + 1]     = acc[mi][ni][1] + b1;
            g_gates[dir][m + 8][j]     = acc[mi][ni][2] + b0;
            g_gates[dir][m + 8][j + 1] = acc[mi][ni][3] + b1;
        }
}

__global__ void lstm_point(int t) {
    int idx = blockIdx.x * 256 + threadIdx.x;
    int dir = idx >> 19;
    int rem = idx & ((1 << 19) - 1);
    int n = rem >> 9, k = rem & 511;
    float gi = g_gates[dir][n][k];
    float gf = g_gates[dir][n][512 + k];
    float gg = g_gates[dir][n][1024 + k];
    float go = g_gates[dir][n][1536 + k];
    float c = g_c[dir][n][k];
    c = sigf(gf) * c + sigf(gi) * tanhfast(gg);
    float h = sigf(go) * tanhfast(c);
    g_c[dir][n][k] = c;
    __nv_bfloat16 hh = __float2bfloat16(h);
    g_Hhi[dir][n][k] = hh;
    g_Hlo[dir][n][k] = __float2bfloat16(h - __bfloat162float(hh));
    if (t == 31) g_feat[n][dir * 512 + k] = h;
}

// phase-2 precompute (fp32 f32x2). rowmap(r)=(r&15)*64+(r>>4)
__global__ __launch_bounds__(256) void pre_gemm(
    const float* __restrict__ W, const float* __restrict__ bias,
    float* __restrict__ out, int N, int sk, int sj)
{
    __shared__ __align__(16) float As2[16][66];
    __shared__ __align__(16) float Bs2[16][130];
    const int tid = threadIdx.x;
    const int tx = tid & 15, ty = tid >> 4;
    const int m0 = blockIdx.y * 64, j0 = blockIdx.x * 128;
    unsigned long long acc[4][4];
#pragma unroll
    for (int i = 0; i < 4; i++)
#pragma unroll
        for (int c = 0; c < 4; c++) acc[i][c] = 0ULL;
    for (int k0 = 0; k0 < 1024; k0 += 16) {
#pragma unroll
        for (int l = 0; l < 4; l++) {
            int idx = tid + 256 * l;
            int k = idx & 15, rr = m0 + (idx >> 4);
            As2[k][idx >> 4] = g_feat[(rr & 15) * 64 + (rr >> 4)][k0 + k];
        }
#pragma unroll
        for (int l = 0; l < 8; l++) {
            int idx = tid + 256 * l;
            int k = idx & 15, j = idx >> 4;
            Bs2[k][j] = W[(k0 + k) * sk + (j0 + j) * sj];
        }
        __syncthreads();
#pragma unroll
        for (int k = 0; k < 16; k++) {
            unsigned long long bv[4];
#pragma unroll
            for (int c = 0; c < 4; c++)
                bv[c] = *reinterpret_cast<const unsigned long long*>(&Bs2[k][2 * tx + 32 * c]);
#pragma unroll
            for (int i = 0; i < 4; i++) {
                unsigned long long av = pk2(As2[k][ty + 16 * i]);
#pragma unroll
                for (int c = 0; c < 4; c++) acc[i][c] = fma2(av, bv[c], acc[i][c]);
            }
        }
        __syncthreads();
    }
#pragma unroll
    for (int i = 0; i < 4; i++) {
        int r = m0 + ty + 16 * i;
#pragma unroll
        for (int c = 0; c < 4; c++) {
            int j = j0 + 2 * tx + 32 * c;
            float2 v = upk2(acc[i][c]);
            out[r * N + j]     = v.x + (bias ? bias[j] : 0.0f);
            out[r * N + j + 1] = v.y + (bias ? bias[j + 1] : 0.0f);
        }
    }
}

__global__ __launch_bounds__(256) void gemm16(
    const float* __restrict__ A1, const float* __restrict__ W1, int K1,
    const float* __restrict__ A2, const float* __restrict__ W2, int K2,
    float* __restrict__ part1, float* __restrict__ part2, int N)
{
    __shared__ float As2[16][18];
    __shared__ float Bs2[16][66];
    const int tid = threadIdx.x;
    const int col = tid & 63, rq = tid >> 6;
    const int ks = blockIdx.y, j0 = blockIdx.x * 64;
    float acc1[4] = {0.f, 0.f, 0.f, 0.f};
    float acc2[4] = {0.f, 0.f, 0.f, 0.f};
    {
        int chunk = K1 >> 2, kb = ks * chunk;
        for (int k0 = 0; k0 < chunk; k0 += 16) {
            { int k = tid & 15, rr = tid >> 4; As2[k][rr] = A1[rr * K1 + kb + k0 + k]; }
#pragma unroll
            for (int l = 0; l < 4; l++) {
                int idx = tid + 256 * l;
                Bs2[idx & 15][idx >> 4] = W1[(j0 + (idx >> 4)) * K1 + kb + k0 + (idx & 15)];
            }
            __syncthreads();
#pragma unroll
            for (int k = 0; k < 16; k++) {
                float b = Bs2[k][col];
#pragma unroll
                for (int i = 0; i < 4; i++) acc1[i] += As2[k][rq * 4 + i] * b;
            }
            __syncthreads();
        }
    }
    {
        int chunk = K2 >> 2, kb = ks * chunk;
        for (int k0 = 0; k0 < chunk; k0 += 16) {
            { int k = tid & 15, rr = tid >> 4; As2[k][rr] = A2[rr * K2 + kb + k0 + k]; }
#pragma unroll
            for (int l = 0; l < 4; l++) {
                int idx = tid + 256 * l;
                Bs2[idx & 15][idx >> 4] = W2[(j0 + (idx >> 4)) * K2 + kb + k0 + (idx & 15)];
            }
            __syncthreads();
#pragma unroll
            for (int k = 0; k < 16; k++) {
                float b = Bs2[k][col];
#pragma unroll
                for (int i = 0; i < 4; i++) acc2[i] += As2[k][rq * 4 + i] * b;
            }
            __syncthreads();
        }
    }
#pragma unroll
    for (int i = 0; i < 4; i++) {
        int rr = rq * 4 + i;
        part1[(ks * 16 + rr) * N + j0 + col] = acc1[i];
        part2[(ks * 16 + rr) * N + j0 + col] = acc2[i];
    }
}

__global__ void gru_combine(
    const float* __restrict__ pre, const float* __restrict__ bih, const float* __restrict__ bhh,
    const float* __restrict__ part1, const float* __restrict__ part2,
    const float* __restrict__ h, float* __restrict__ out, float* __restrict__ out2, int Dh)
{
    int idx = blockIdx.x * 256 + threadIdx.x;
    if (idx >= 16 * Dh) return;
    int b = idx / Dh, j = idx - b * Dh;
    int G = 3 * Dh;
    float gir = 0.f, giz = 0.f, gin = 0.f, ghr = 0.f, ghz = 0.f, ghn = 0.f;
#pragma unroll
    for (int ks = 0; ks < 4; ks++) {
        const float* p1 = part1 + (ks * 16 + b) * G;
        const float* p2 = part2 + (ks * 16 + b) * G;
        gir += p1[j]; giz += p1[Dh + j]; gin += p1[2 * Dh + j];
        ghr += p2[j]; ghz += p2[Dh + j]; ghn += p2[2 * Dh + j];
    }
    if (pre) {
        const float* pp = pre + b * G;
        gir += pp[j]; giz += pp[Dh + j]; gin += pp[2 * Dh + j];
    } else {
        gir += bih[j]; giz += bih[Dh + j]; gin += bih[2 * Dh + j];
    }
    ghr += bhh[j]; ghz += bhh[Dh + j]; ghn += bhh[2 * Dh + j];
    float rg = sigf(gir + ghr);
    float z = sigf(giz + ghz);
    float n = tanhfast(gin + rg * ghn);
    float o = (1.0f - z) * n + z * h[idx];
    out[idx] = o;
    if (out2) out2[idx] = o;
}

__global__ void attn_kernel(int i) {
    __shared__ float q_s[1024];
    __shared__ float sc[65];
    const int b = blockIdx.x, tid = threadIdx.x;
#pragma unroll
    for (int l = 0; l < 4; l++) q_s[tid + 256 * l] = g_q[i][b][tid + 256 * l];
    __syncthreads();
    const int wid = tid >> 5, lane = tid & 31;
    for (int t = wid; t <= i; t += 8) {
        float s = 0.0f;
        for (int d = lane; d < 1024; d += 32) s += q_s[d] * g_hist[t][b][d];
#pragma unroll
        for (int o = 16; o; o >>= 1) s += __shfl_xor_sync(0xffffffffu, s, o);
        if (lane == 0) sc[t] = s;
    }
    __syncthreads();
    if (tid < 32) {
        float m = -1e30f;
        for (int t = lane; t <= i; t += 32) m = fmaxf(m, sc[t]);
#pragma unroll
        for (int o = 16; o; o >>= 1) m = fmaxf(m, __shfl_xor_sync(0xffffffffu, m, o));
        float s = 0.0f;
        for (int t = lane; t <= i; t += 32) { float e = __expf(sc[t] - m); sc[t] = e; s += e; }
#pragma unroll
        for (int o = 16; o; o >>= 1) s += __shfl_xor_sync(0xffffffffu, s, o);
        float inv = 1.0f / s;
        for (int t = lane; t <= i; t += 32) sc[t] *= inv;
    }
    __syncthreads();
#pragma unroll
    for (int l = 0; l < 4; l++) {
        int d = tid + 256 * l;
        float a = 0.0f;
        for (int t = 0; t <= i; t++) a += sc[t] * g_hist[t][b][d];
        g_ctx[b][d] = a;
    }
}

__global__ void cls_kernel(const float* __restrict__ cls_W, const float* __restrict__ cls_b,
                           float* __restrict__ out) {
    int u = blockIdx.x, tid = threadIdx.x;
    if (tid >= 112) return;
    int b = tid / 7, c = tid - b * 7;
    float s = cls_b[c];
    const float* w = cls_W + c * 512;
    const float* e = &g_es[u][b][0];
    for (int k = 0; k < 512; k++) s += e[k] * w[k];
    out[(b * 64 + u) * 7 + c] = s;
}

extern "C" void kernel_launch(void* const* d_in, const int* in_sizes, int n_in,
                              void* d_out, int out_size) {
    const float* x      = (const float*)d_in[0];
    const float* lWih_f = (const float*)d_in[1];
    const float* lWhh_f = (const float*)d_in[2];
    const float* lbih_f = (const float*)d_in[3];
    const float* lbhh_f = (const float*)d_in[4];
    const float* lWih_b = (const float*)d_in[5];
    const float* lWhh_b = (const float*)d_in[6];
    const float* lbih_b = (const float*)d_in[7];
    const float* lbhh_b = (const float*)d_in[8];
    const float* gg_Wih = (const float*)d_in[9];
    const float* gg_Whh = (const float*)d_in[10];
    const float* gg_bhh = (const float*)d_in[12];
    const float* Wg     = (const float*)d_in[13];
    const float* pg_Wih = (const float*)d_in[14];
    const float* pg_Whh = (const float*)d_in[15];
    const float* pg_bhh = (const float*)d_in[17];
    const float* eg_Wih = (const float*)d_in[18];
    const float* eg_Whh = (const float*)d_in[19];
    const float* eg_bih = (const float*)d_in[20];
    const float* eg_bhh = (const float*)d_in[21];
    const float* cls_W  = (const float*)d_in[22];
    const float* cls_b  = (const float*)d_in[23];
    const float* gg_bih = (const float*)d_in[11];
    const float* pg_bih = (const float*)d_in[16];
    float* out = (float*)d_out;

    float *pAgg, *pApg, *pQ, *pHist, *pP0, *pP1, *pCtx, *pE, *pEs;
    float *pP1a, *pP1b, *pP2a, *pP2b, *pP3a, *pP3b;
    cudaGetSymbolAddress((void**)&pAgg, g_Agg);
    cudaGetSymbolAddress((void**)&pApg, g_Apg);
    cudaGetSymbolAddress((void**)&pQ, g_q);
    cudaGetSymbolAddress((void**)&pHist, g_hist);
    cudaGetSymbolAddress((void**)&pP0, g_p0);
    cudaGetSymbolAddress((void**)&pP1, g_p1);
    cudaGetSymbolAddress((void**)&pCtx, g_ctx);
    cudaGetSymbolAddress((void**)&pE, g_e);
    cudaGetSymbolAddress((void**)&pEs, g_es);
    cudaGetSymbolAddress((void**)&pP1a, g_P1a);
    cudaGetSymbolAddress((void**)&pP1b, g_P1b);
    cudaGetSymbolAddress((void**)&pP2a, g_P2a);
    cudaGetSymbolAddress((void**)&pP2b, g_P2b);
    cudaGetSymbolAddress((void**)&pP3a, g_P3a);
    cudaGetSymbolAddress((void**)&pP3b, g_P3b);

    zero_kernel<<<4160, 256>>>();
    convert_kernel<<<40960, 256>>>(x, lWih_f, lWhh_f, lWih_b, lWhh_b);

    for (int t = 0; t < 32; t++) {
        lstm_tc<<<dim3(16, 8, 2), 256>>>(lbih_f, lbhh_f, lbih_b, lbhh_b, t);
        lstm_point<<<4096, 256>>>(t);
    }

    pre_gemm<<<dim3(24, 16), 256>>>(gg_Wih, gg_bih, pAgg, 3072, 1, 1024);
    pre_gemm<<<dim3(24, 16), 256>>>(pg_Wih, pg_bih, pApg, 3072, 1, 1024);
    pre_gemm<<<dim3(8, 16), 256>>>(Wg, nullptr, pQ, 1024, 1024, 1);

    for (int i = 0; i < 64; i++) {
        float* p_slot = ((i & 1) == 0) ? pP0 : pP1;
        float* hist_i = pHist + (size_t)i * 16 * 1024;
        float* hist_i1 = pHist + (size_t)(i + 1) * 16 * 1024;

        gemm16<<<dim3(48, 4), 256>>>(p_slot, gg_Wih, 1024, hist_i, gg_Whh, 1024, pP1a, pP1b, 3072);
        gru_combine<<<64, 256>>>(pAgg + (size_t)i * 16 * 3072, nullptr, gg_bhh,
                                 pP1a, pP1b, hist_i, hist_i1, nullptr, 1024);
        attn_kernel<<<16, 256>>>(i);
        gemm16<<<dim3(48, 4), 256>>>(pCtx, pg_Wih, 1024, p_slot, pg_Whh, 1024, pP2a, pP2b, 3072);
        gru_combine<<<64, 256>>>(pApg + (size_t)i * 16 * 3072, nullptr, pg_bhh,
                                 pP2a, pP2b, p_slot, p_slot, nullptr, 1024);
        gemm16<<<dim3(24, 4), 256>>>(p_slot, eg_Wih, 1024, pE, eg_Whh, 512, pP3a, pP3b, 1536);
        gru_combine<<<32, 256>>>(nullptr, eg_bih, eg_bhh, pP3a, pP3b, pE, pE,
                                 pEs + (size_t)i * 16 * 512, 512);
    }

    cls_kernel<<<64, 128>>>(cls_W, cls_b, out);
}

// round 8
// speedup vs baseline: 1.2764x; 1.0261x over previous
#include <cuda_runtime.h>
#include <cuda_bf16.h>

// B=16,U=64,W=32,E=300,H=512,Hh=512,C=7,D=1024,N=1024. KPAD=320+512=832.

__device__ float g_c[2][1024][512];
__device__ float g_feat[1024][1024];
__device__ float g_bias[2][2048];                 // permuted bih+bhh, j'=4k+g
__device__ __nv_bfloat16 g_Xhi[32][1024][320];
__device__ __nv_bfloat16 g_Xlo[32][1024][320];
__device__ __nv_bfloat16 g_Whi[2][2048][832];     // rows permuted j'=4k+g
__device__ __nv_bfloat16 g_Wlo[2][2048][832];
__device__ __nv_bfloat16 g_Hhi[2][1024][512];
__device__ __nv_bfloat16 g_Hlo[2][1024][512];
__device__ float g_Agg[64][16][3072];
__device__ float g_Apg[64][16][3072];
__device__ float g_q[64][16][1024];
__device__ float g_hist[65][16][1024];
__device__ float g_p0[16][1024];
__device__ float g_p1[16][1024];
__device__ float g_e[16][512];
__device__ float g_ctx[16][1024];
__device__ float g_es[64][16][512];
__device__ float g_P1a[4][16][3072];
__device__ float g_P1b[4][16][3072];
__device__ float g_P2a[4][16][3072];
__device__ float g_P2b[4][16][3072];
__device__ float g_P3a[4][16][1536];
__device__ float g_P3b[4][16][1536];

__device__ __forceinline__ unsigned long long pk2(float v) {
    unsigned long long r; asm("mov.b64 %0, {%1, %1};" : "=l"(r) : "f"(v)); return r;
}
__device__ __forceinline__ unsigned long long fma2(unsigned long long a, unsigned long long b, unsigned long long c) {
    unsigned long long d; asm("fma.rn.f32x2 %0, %1, %2, %3;" : "=l"(d) : "l"(a), "l"(b), "l"(c)); return d;
}
__device__ __forceinline__ float2 upk2(unsigned long long v) {
    float2 f; asm("mov.b64 {%0, %1}, %2;" : "=f"(f.x), "=f"(f.y) : "l"(v)); return f;
}
__device__ __forceinline__ float sigf(float x) { return 1.0f / (1.0f + __expf(-x)); }
__device__ __forceinline__ float tanhfast(float x) { return 2.0f / (1.0f + __expf(-2.0f * x)) - 1.0f; }
__device__ __forceinline__ unsigned sm_u32(const void* p) { return (unsigned)__cvta_generic_to_shared(p); }
__device__ __forceinline__ void ldsm4(unsigned& r0, unsigned& r1, unsigned& r2, unsigned& r3, unsigned a) {
    asm volatile("ldmatrix.sync.aligned.m8n8.x4.shared.b16 {%0,%1,%2,%3},[%4];"
                 : "=r"(r0), "=r"(r1), "=r"(r2), "=r"(r3) : "r"(a));
}
__device__ __forceinline__ void mma_bf16(float c[4], unsigned a0, unsigned a1, unsigned a2, unsigned a3,
                                         unsigned b0, unsigned b1) {
    asm volatile("mma.sync.aligned.m16n8k16.row.col.f32.bf16.bf16.f32 "
                 "{%0,%1,%2,%3},{%4,%5,%6,%7},{%8,%9},{%0,%1,%2,%3};"
                 : "+f"(c[0]), "+f"(c[1]), "+f"(c[2]), "+f"(c[3])
                 : "r"(a0), "r"(a1), "r"(a2), "r"(a3), "r"(b0), "r"(b1));
}

__global__ void zero_kernel() {
    int i = blockIdx.x * 256 + threadIdx.x;
    if (i < 2 * 1024 * 512) {
        (&g_c[0][0][0])[i] = 0.0f;
        (&g_Hhi[0][0][0])[i] = __float2bfloat16(0.0f);
        (&g_Hlo[0][0][0])[i] = __float2bfloat16(0.0f);
    }
    if (i < 65 * 16 * 1024) (&g_hist[0][0][0])[i] = 0.0f;
    if (i < 16 * 1024) { (&g_p0[0][0])[i] = 0.0f; (&g_p1[0][0])[i] = 0.0f; }
    if (i < 16 * 512) (&g_e[0][0])[i] = 0.0f;
}

// split x/weights into bf16 hi/lo. W rows permuted: out row j'=4k+g <- in row g*512+k.
__global__ void convert_kernel(const float* __restrict__ x,
                               const float* __restrict__ Wfi, const float* __restrict__ Wfh,
                               const float* __restrict__ Wbi, const float* __restrict__ Wbh,
                               const float* __restrict__ bif, const float* __restrict__ bhf,
                               const float* __restrict__ bib, const float* __restrict__ bhb) {
    int i = blockIdx.x * 256 + threadIdx.x;
    if (i < 32 * 1024 * 320) {
        int e = i % 320, r = i / 320;
        int n = r % 1024, t = r / 1024;
        float v = (e < 300) ? x[n * 9600 + t * 300 + e] : 0.0f;
        __nv_bfloat16 h = __float2bfloat16(v);
        (&g_Xhi[0][0][0])[i] = h;
        (&g_Xlo[0][0][0])[i] = __float2bfloat16(v - __bfloat162float(h));
    }
    if (i < 2 * 2048 * 832) {
        int k = i % 832, r = i / 832;
        int jp = r % 2048, d = r / 2048;
        int row = (jp & 3) * 512 + (jp >> 2);
        const float* Wih = d ? Wbi : Wfi;
        const float* Whh = d ? Wbh : Wfh;
        float v = (k < 300) ? Wih[row * 300 + k] : (k < 320 ? 0.0f : Whh[row * 512 + (k - 320)]);
        __nv_bfloat16 h = __float2bfloat16(v);
        (&g_Whi[0][0][0])[i] = h;
        (&g_Wlo[0][0][0])[i] = __float2bfloat16(v - __bfloat162float(h));
    }
    if (i < 2 * 2048) {
        int d = i >> 11, jp = i & 2047;
        int row = (jp & 3) * 512 + (jp >> 2);
        g_bias[d][jp] = (d ? bib[row] + bhb[row] : bif[row] + bhf[row]);
    }
}

// Fused tensor-core LSTM step: GEMM (bf16 hi/lo, 3-pass) + cell pointwise.
// grid (16,8,2), 256 threads. Block 128x128 (j'=4k+g cols -> 32 hidden units).
__global__ __launch_bounds__(256) void lstm_tc(int t, int last) {
    extern __shared__ char smraw[];
    __nv_bfloat16* As = (__nv_bfloat16*)smraw;              // [2][128][24]
    __nv_bfloat16* Bs = (__nv_bfloat16*)(smraw + 12288);    // [2][128][24]
    float* sg = (float*)smraw;                              // [128][132] (reused)

    const int dir = blockIdx.z, m0 = blockIdx.y * 128, n0 = blockIdx.x * 128;
    const int tt = dir ? 31 - t : t;
    const int tid = threadIdx.x, lane = tid & 31, wid = tid >> 5;
    const int wm = wid >> 2, wn = wid & 3;
    const int r = tid >> 1, hf = (tid & 1) * 8;

    const __nv_bfloat16* xhi = &g_Xhi[tt][m0 + r][hf];
    const __nv_bfloat16* xlo = &g_Xlo[tt][m0 + r][hf];
    const __nv_bfloat16* hhi = &g_Hhi[dir][m0 + r][hf];
    const __nv_bfloat16* hlo = &g_Hlo[dir][m0 + r][hf];
    const __nv_bfloat16* whi = &g_Whi[dir][n0 + r][hf];
    const __nv_bfloat16* wlo = &g_Wlo[dir][n0 + r][hf];

    float acc[4][4][4];
#pragma unroll
    for (int mi = 0; mi < 4; mi++)
#pragma unroll
        for (int ni = 0; ni < 4; ni++)
#pragma unroll
            for (int q = 0; q < 4; q++) acc[mi][ni][q] = 0.0f;

    uint4 ra, rb;
    auto fetch = [&](int kkn) {
        int pass = (kkn >= 52) + (kkn >= 104);
        int k = (kkn - pass * 52) * 16;
        const __nv_bfloat16* ap;
        if (k < 320) ap = (pass == 1 ? xlo : xhi) + k;
        else         ap = (pass == 1 ? hlo : hhi) + (k - 320);
        const __nv_bfloat16* bp = (pass == 2 ? wlo : whi) + k;
        ra = *(const uint4*)ap;
        rb = *(const uint4*)bp;
    };

    fetch(0);
    *(uint4*)&As[(0 * 128 + r) * 24 + hf] = ra;
    *(uint4*)&Bs[(0 * 128 + r) * 24 + hf] = rb;
    __syncthreads();

    for (int kk = 0; kk < 156; kk++) {
        int cur = kk & 1;
        if (kk < 155) fetch(kk + 1);

        unsigned a[4][4], bfr[2][4];
#pragma unroll
        for (int mi = 0; mi < 4; mi++) {
            unsigned ad = sm_u32(&As[(cur * 128 + wm * 64 + mi * 16 + (lane & 15)) * 24 + (lane >> 4) * 8]);
            ldsm4(a[mi][0], a[mi][1], a[mi][2], a[mi][3], ad);
        }
#pragma unroll
        for (int nb = 0; nb < 2; nb++) {
            unsigned ad = sm_u32(&Bs[(cur * 128 + wn * 32 + nb * 16 + (lane & 15)) * 24 + (lane >> 4) * 8]);
            ldsm4(bfr[nb][0], bfr[nb][1], bfr[nb][2], bfr[nb][3], ad);
        }
#pragma unroll
        for (int mi = 0; mi < 4; mi++)
#pragma unroll
            for (int ni = 0; ni < 4; ni++)
                mma_bf16(acc[mi][ni], a[mi][0], a[mi][1], a[mi][2], a[mi][3],
                         bfr[ni >> 1][ni & 1], bfr[ni >> 1][(ni & 1) + 2]);

        if (kk < 155) {
            *(uint4*)&As[((cur ^ 1) * 128 + r) * 24 + hf] = ra;
            *(uint4*)&Bs[((cur ^ 1) * 128 + r) * 24 + hf] = rb;
        }
        __syncthreads();
    }

    // epilogue: dump frags to smem, then fused LSTM cell pointwise
#pragma unroll
    for (int mi = 0; mi < 4; mi++)
#pragma unroll
        for (int ni = 0; ni < 4; ni++) {
            int mm = wm * 64 + mi * 16 + (lane >> 2);
            int jj = wn * 32 + ni * 8 + (lane & 3) * 2;
            sg[mm * 132 + jj]       = acc[mi][ni][0];
            sg[mm * 132 + jj + 1]   = acc[mi][ni][1];
            sg[(mm + 8) * 132 + jj]     = acc[mi][ni][2];
            sg[(mm + 8) * 132 + jj + 1] = acc[mi][ni][3];
        }
    __syncthreads();

#pragma unroll
    for (int l = 0; l < 16; l++) {
        int idx = tid + 256 * l;
        int m = idx >> 5, kk = idx & 31;
        float4 gq = *(float4*)&sg[m * 132 + 4 * kk];
        float4 bq = *(const float4*)&g_bias[dir][n0 + 4 * kk];
        float gi = gq.x + bq.x;
        float gf = gq.y + bq.y;
        float gg = gq.z + bq.z;
        float go = gq.w + bq.w;
        int kglob = (n0 >> 2) + kk;
        int mg = m0 + m;
        float c = g_c[dir][mg][kglob];
        c = sigf(gf) * c + sigf(gi) * tanhfast(gg);
        float h = sigf(go) * tanhfast(c);
        g_c[dir][mg][kglob] = c;
        __nv_bfloat16 hh = __float2bfloat16(h);
        g_Hhi[dir][mg][kglob] = hh;
        g_Hlo[dir][mg][kglob] = __float2bfloat16(h - __bfloat162float(hh));
        if (last) g_feat[mg][dir * 512 + kglob] = h;
    }
}

// ---------------- phase 2 (identical to passing R6 code) -------------------
__global__ __launch_bounds__(256) void pre_gemm(
    const float* __restrict__ W, const float* __restrict__ bias,
    float* __restrict__ out, int N, int sk, int sj)
{
    __shared__ __align__(16) float As2[16][66];
    __shared__ __align__(16) float Bs2[16][130];
    const int tid = threadIdx.x;
    const int tx = tid & 15, ty = tid >> 4;
    const int m0 = blockIdx.y * 64, j0 = blockIdx.x * 128;
    unsigned long long acc[4][4];
#pragma unroll
    for (int i = 0; i < 4; i++)
#pragma unroll
        for (int c = 0; c < 4; c++) acc[i][c] = 0ULL;
    for (int k0 = 0; k0 < 1024; k0 += 16) {
#pragma unroll
        for (int l = 0; l < 4; l++) {
            int idx = tid + 256 * l;
            int k = idx & 15, rr = m0 + (idx >> 4);
            As2[k][idx >> 4] = g_feat[(rr & 15) * 64 + (rr >> 4)][k0 + k];
        }
#pragma unroll
        for (int l = 0; l < 8; l++) {
            int idx = tid + 256 * l;
            int k = idx & 15, j = idx >> 4;
            Bs2[k][j] = W[(k0 + k) * sk + (j0 + j) * sj];
        }
        __syncthreads();
#pragma unroll
        for (int k = 0; k < 16; k++) {
            unsigned long long bv[4];
#pragma unroll
            for (int c = 0; c < 4; c++)
                bv[c] = *reinterpret_cast<const unsigned long long*>(&Bs2[k][2 * tx + 32 * c]);
#pragma unroll
            for (int i = 0; i < 4; i++) {
                unsigned long long av = pk2(As2[k][ty + 16 * i]);
#pragma unroll
                for (int c = 0; c < 4; c++) acc[i][c] = fma2(av, bv[c], acc[i][c]);
            }
        }
        __syncthreads();
    }
#pragma unroll
    for (int i = 0; i < 4; i++) {
        int r = m0 + ty + 16 * i;
#pragma unroll
        for (int c = 0; c < 4; c++) {
            int j = j0 + 2 * tx + 32 * c;
            float2 v = upk2(acc[i][c]);
            out[r * N + j]     = v.x + (bias ? bias[j] : 0.0f);
            out[r * N + j + 1] = v.y + (bias ? bias[j + 1] : 0.0f);
        }
    }
}

__global__ __launch_bounds__(256) void gemm16(
    const float* __restrict__ A1, const float* __restrict__ W1, int K1,
    const float* __restrict__ A2, const float* __restrict__ W2, int K2,
    float* __restrict__ part1, float* __restrict__ part2, int N)
{
    __shared__ float As2[16][18];
    __shared__ float Bs2[16][66];
    const int tid = threadIdx.x;
    const int col = tid & 63, rq = tid >> 6;
    const int ks = blockIdx.y, j0 = blockIdx.x * 64;
    float acc1[4] = {0.f, 0.f, 0.f, 0.f};
    float acc2[4] = {0.f, 0.f, 0.f, 0.f};
    {
        int chunk = K1 >> 2, kb = ks * chunk;
        for (int k0 = 0; k0 < chunk; k0 += 16) {
            { int k = tid & 15, rr = tid >> 4; As2[k][rr] = A1[rr * K1 + kb + k0 + k]; }
#pragma unroll
            for (int l = 0; l < 4; l++) {
                int idx = tid + 256 * l;
                Bs2[idx & 15][idx >> 4] = W1[(j0 + (idx >> 4)) * K1 + kb + k0 + (idx & 15)];
            }
            __syncthreads();
#pragma unroll
            for (int k = 0; k < 16; k++) {
                float b = Bs2[k][col];
#pragma unroll
                for (int i = 0; i < 4; i++) acc1[i] += As2[k][rq * 4 + i] * b;
            }
            __syncthreads();
        }
    }
    {
        int chunk = K2 >> 2, kb = ks * chunk;
        for (int k0 = 0; k0 < chunk; k0 += 16) {
            { int k = tid & 15, rr = tid >> 4; As2[k][rr] = A2[rr * K2 + kb + k0 + k]; }
#pragma unroll
            for (int l = 0; l < 4; l++) {
                int idx = tid + 256 * l;
                Bs2[idx & 15][idx >> 4] = W2[(j0 + (idx >> 4)) * K2 + kb + k0 + (idx & 15)];
            }
            __syncthreads();
#pragma unroll
            for (int k = 0; k < 16; k++) {
                float b = Bs2[k][col];
#pragma unroll
                for (int i = 0; i < 4; i++) acc2[i] += As2[k][rq * 4 + i] * b;
            }
            __syncthreads();
        }
    }
#pragma unroll
    for (int i = 0; i < 4; i++) {
        int rr = rq * 4 + i;
        part1[(ks * 16 + rr) * N + j0 + col] = acc1[i];
        part2[(ks * 16 + rr) * N + j0 + col] = acc2[i];
    }
}

__global__ void gru_combine(
    const float* __restrict__ pre, const float* __restrict__ bih, const float* __restrict__ bhh,
    const float* __restrict__ part1, const float* __restrict__ part2,
    const float* __restrict__ h, float* __restrict__ out, float* __restrict__ out2, int Dh)
{
    int idx = blockIdx.x * 256 + threadIdx.x;
    if (idx >= 16 * Dh) return;
    int b = idx / Dh, j = idx - b * Dh;
    int G = 3 * Dh;
    float gir = 0.f, giz = 0.f, gin = 0.f, ghr = 0.f, ghz = 0.f, ghn = 0.f;
#pragma unroll
    for (int ks = 0; ks < 4; ks++) {
        const float* p1 = part1 + (ks * 16 + b) * G;
        const float* p2 = part2 + (ks * 16 + b) * G;
        gir += p1[j]; giz += p1[Dh + j]; gin += p1[2 * Dh + j];
        ghr += p2[j]; ghz += p2[Dh + j]; ghn += p2[2 * Dh + j];
    }
    if (pre) {
        const float* pp = pre + b * G;
        gir += pp[j]; giz += pp[Dh + j]; gin += pp[2 * Dh + j];
    } else {
        gir += bih[j]; giz += bih[Dh + j]; gin += bih[2 * Dh + j];
    }
    ghr += bhh[j]; ghz += bhh[Dh + j]; ghn += bhh[2 * Dh + j];
    float rg = sigf(gir + ghr);
    float z = sigf(giz + ghz);
    float n = tanhfast(gin + rg * ghn);
    float o = (1.0f - z) * n + z * h[idx];
    out[idx] = o;
    if (out2) out2[idx] = o;
}

__global__ void attn_kernel(int i) {
    __shared__ float q_s[1024];
    __shared__ float sc[65];
    const int b = blockIdx.x, tid = threadIdx.x;
#pragma unroll
    for (int l = 0; l < 4; l++) q_s[tid + 256 * l] = g_q[i][b][tid + 256 * l];
    __syncthreads();
    const int wid = tid >> 5, lane = tid & 31;
    for (int t = wid; t <= i; t += 8) {
        float s = 0.0f;
        for (int d = lane; d < 1024; d += 32) s += q_s[d] * g_hist[t][b][d];
#pragma unroll
        for (int o = 16; o; o >>= 1) s += __shfl_xor_sync(0xffffffffu, s, o);
        if (lane == 0) sc[t] = s;
    }
    __syncthreads();
    if (tid < 32) {
        float m = -1e30f;
        for (int t = lane; t <= i; t += 32) m = fmaxf(m, sc[t]);
#pragma unroll
        for (int o = 16; o; o >>= 1) m = fmaxf(m, __shfl_xor_sync(0xffffffffu, m, o));
        float s = 0.0f;
        for (int t = lane; t <= i; t += 32) { float e = __expf(sc[t] - m); sc[t] = e; s += e; }
#pragma unroll
        for (int o = 16; o; o >>= 1) s += __shfl_xor_sync(0xffffffffu, s, o);
        float inv = 1.0f / s;
        for (int t = lane; t <= i; t += 32) sc[t] *= inv;
    }
    __syncthreads();
#pragma unroll
    for (int l = 0; l < 4; l++) {
        int d = tid + 256 * l;
        float a = 0.0f;
        for (int t = 0; t <= i; t++) a += sc[t] * g_hist[t][b][d];
        g_ctx[b][d] = a;
    }
}

__global__ void cls_kernel(const float* __restrict__ cls_W, const float* __restrict__ cls_b,
                           float* __restrict__ out) {
    int u = blockIdx.x, tid = threadIdx.x;
    if (tid >= 112) return;
    int b = tid / 7, c = tid - b * 7;
    float s = cls_b[c];
    const float* w = cls_W + c * 512;
    const float* e = &g_es[u][b][0];
    for (int k = 0; k < 512; k++) s += e[k] * w[k];
    out[(b * 64 + u) * 7 + c] = s;
}

extern "C" void kernel_launch(void* const* d_in, const int* in_sizes, int n_in,
                              void* d_out, int out_size) {
    const float* x      = (const float*)d_in[0];
    const float* lWih_f = (const float*)d_in[1];
    const float* lWhh_f = (const float*)d_in[2];
    const float* lbih_f = (const float*)d_in[3];
    const float* lbhh_f = (const float*)d_in[4];
    const float* lWih_b = (const float*)d_in[5];
    const float* lWhh_b = (const float*)d_in[6];
    const float* lbih_b = (const float*)d_in[7];
    const float* lbhh_b = (const float*)d_in[8];
    const float* gg_Wih = (const float*)d_in[9];
    const float* gg_Whh = (const float*)d_in[10];
    const float* gg_bih = (const float*)d_in[11];
    const float* gg_bhh = (const float*)d_in[12];
    const float* Wg     = (const float*)d_in[13];
    const float* pg_Wih = (const float*)d_in[14];
    const float* pg_Whh = (const float*)d_in[15];
    const float* pg_bih = (const float*)d_in[16];
    const float* pg_bhh = (const float*)d_in[17];
    const float* eg_Wih = (const float*)d_in[18];
    const float* eg_Whh = (const float*)d_in[19];
    const float* eg_bih = (const float*)d_in[20];
    const float* eg_bhh = (const float*)d_in[21];
    const float* cls_W  = (const float*)d_in[22];
    const float* cls_b  = (const float*)d_in[23];
    float* out = (float*)d_out;

    float *pAgg, *pApg, *pQ, *pHist, *pP0, *pP1, *pCtx, *pE, *pEs;
    float *pP1a, *pP1b, *pP2a, *pP2b, *pP3a, *pP3b;
    cudaGetSymbolAddress((void**)&pAgg, g_Agg);
    cudaGetSymbolAddress((void**)&pApg, g_Apg);
    cudaGetSymbolAddress((void**)&pQ, g_q);
    cudaGetSymbolAddress((void**)&pHist, g_hist);
    cudaGetSymbolAddress((void**)&pP0, g_p0);
    cudaGetSymbolAddress((void**)&pP1, g_p1);
    cudaGetSymbolAddress((void**)&pCtx, g_ctx);
    cudaGetSymbolAddress((void**)&pE, g_e);
    cudaGetSymbolAddress((void**)&pEs, g_es);
    cudaGetSymbolAddress((void**)&pP1a, g_P1a);
    cudaGetSymbolAddress((void**)&pP1b, g_P1b);
    cudaGetSymbolAddress((void**)&pP2a, g_P2a);
    cudaGetSymbolAddress((void**)&pP2b, g_P2b);
    cudaGetSymbolAddress((void**)&pP3a, g_P3a);
    cudaGetSymbolAddress((void**)&pP3b, g_P3b);

    static int smem_set = 0;
    if (!smem_set) {
        cudaFuncSetAttribute(lstm_tc, cudaFuncAttributeMaxDynamicSharedMemorySize, 128 * 132 * 4);
        smem_set = 1;
    }

    zero_kernel<<<4160, 256>>>();
    convert_kernel<<<40960, 256>>>(x, lWih_f, lWhh_f, lWih_b, lWhh_b,
                                   lbih_f, lbhh_f, lbih_b, lbhh_b);

    for (int t = 0; t < 32; t++)
        lstm_tc<<<dim3(16, 8, 2), 256, 128 * 132 * 4>>>(t, t == 31);

    pre_gemm<<<dim3(24, 16), 256>>>(gg_Wih, gg_bih, pAgg, 3072, 1, 1024);
    pre_gemm<<<dim3(24, 16), 256>>>(pg_Wih, pg_bih, pApg, 3072, 1, 1024);
    pre_gemm<<<dim3(8, 16), 256>>>(Wg, nullptr, pQ, 1024, 1024, 1);

    for (int i = 0; i < 64; i++) {
        float* p_slot = ((i & 1) == 0) ? pP0 : pP1;
        float* hist_i = pHist + (size_t)i * 16 * 1024;
        float* hist_i1 = pHist + (size_t)(i + 1) * 16 * 1024;

        gemm16<<<dim3(48, 4), 256>>>(p_slot, gg_Wih, 1024, hist_i, gg_Whh, 1024, pP1a, pP1b, 3072);
        gru_combine<<<64, 256>>>(pAgg + (size_t)i * 16 * 3072, nullptr, gg_bhh,
                                 pP1a, pP1b, hist_i, hist_i1, nullptr, 1024);
        attn_kernel<<<16, 256>>>(i);
        gemm16<<<dim3(48, 4), 256>>>(pCtx, pg_Wih, 1024, p_slot, pg_Whh, 1024, pP2a, pP2b, 3072);
        gru_combine<<<64, 256>>>(pApg + (size_t)i * 16 * 3072, nullptr, pg_bhh,
                                 pP2a, pP2b, p_slot, p_slot, nullptr, 1024);
        gemm16<<<dim3(24, 4), 256>>>(p_slot, eg_Wih, 1024, pE, eg_Whh, 512, pP3a, pP3b, 1536);
        gru_combine<<<32, 256>>>(nullptr, eg_bih, eg_bhh, pP3a, pP3b, pE, pE,
                                 pEs + (size_t)i * 16 * 512, 512);
    }

    cls_kernel<<<64, 128>>>(cls_W, cls_b, out);
}